// round 6
// baseline (speedup 1.0000x reference)
#include <cuda_runtime.h>

#define BB 64
#define SS 256
#define TT 8
#define DD 256
#define E_EDGES 500000
#define M_CNT 2048
#define ROW_STRIDE (TT * DD)   // 2048 floats between consecutive (b,s) type rows
#define NEG_INF_F (-10000000000.0f)

#define S_TILE 32
#define N_TILES (SS / S_TILE)            // 8
#define LM_BLOCKS (BB * N_TILES)          // 512
#define LEMMA_BLOCKS 2048
#define TOTAL_BLOCKS (LEMMA_BLOCKS + LM_BLOCKS)
#define BATCH_CAP 128                     // max m's per batch (mean 32, 17-sigma safe)

// Folded linear head: v = w1 @ w2 (D floats), c = b1.w2 + b2
__device__ float g_v[DD];
__device__ float g_c;
// Per-batch m lists (rebuilt every launch; order within a batch is irrelevant)
__device__ int g_cnt[BB];
__device__ int g_list[BB * BATCH_CAP];

// ---------------------------------------------------------------------------
// Prep: fold the two linear layers, zero the batch counters.
// ---------------------------------------------------------------------------
__global__ void prep_kernel(const float* __restrict__ w1,   // [D, D/2]
                            const float* __restrict__ b1,   // [D/2]
                            const float* __restrict__ w2,   // [D/2, 1]
                            const float* __restrict__ b2) { // [1]
    int d = threadIdx.x;  // 0..255
    if (d < BB) g_cnt[d] = 0;
    float acc = 0.f;
    #pragma unroll 8
    for (int k = 0; k < DD / 2; k++)
        acc = fmaf(w1[d * (DD / 2) + k], w2[k], acc);
    g_v[d] = acc;
    if (d == 0) {
        float c = b2[0];
        for (int k = 0; k < DD / 2; k++)
            c = fmaf(b1[k], w2[k], c);
        g_c = c;
    }
}

// Bucket m indices by batch pointer.
__global__ void bucket_kernel(const int* __restrict__ bptr) {
    int m = blockIdx.x * blockDim.x + threadIdx.x;
    if (m < M_CNT) {
        int b = bptr[m];
        int slot = atomicAdd(&g_cnt[b], 1);
        if (slot < BATCH_CAP) g_list[b * BATCH_CAP + slot] = m;
    }
}

__device__ __forceinline__ float warp_reduce_sum(float v) {
    #pragma unroll
    for (int off = 16; off > 0; off >>= 1)
        v += __shfl_xor_sync(0xFFFFFFFFu, v, off);
    return v;
}

__device__ __forceinline__ float4 ldcs4(const float4* p) {
    return __ldcs(p);   // evict-streaming: don't thrash L1 tiles of lm blocks
}

// ---------------------------------------------------------------------------
// Lemma phase: warp per 2 edges (8 independent LDG.128 in flight for MLP).
// lane covers d = lane*4 and 128+lane*4: fully coalesced 512B warp segments.
// ---------------------------------------------------------------------------
__device__ __forceinline__ void lemma_phase(
    const float* __restrict__ tok, const int* __restrict__ eidx,
    float* __restrict__ out, int block)
{
    const int lane   = threadIdx.x & 31;
    const int warp   = (block * blockDim.x + threadIdx.x) >> 5;
    const int nwarps = (LEMMA_BLOCKS * blockDim.x) >> 5;

    const float4* vv = reinterpret_cast<const float4*>(g_v);
    const float4 v0 = vv[lane];
    const float4 v1 = vv[32 + lane];
    const float  c  = g_c;

    // E_EDGES is even: iterate over pairs.
    for (int p = warp; p < E_EDGES / 2; p += nwarps) {
        const int e0 = 2 * p;
        const int e1 = e0 + 1;
        const int sA = eidx[e0];
        const int gA = eidx[E_EDGES + e0];
        const int sB = eidx[e1];
        const int gB = eidx[E_EDGES + e1];

        const float4* rsA = reinterpret_cast<const float4*>(tok + (size_t)sA * ROW_STRIDE);
        const float4* rgA = reinterpret_cast<const float4*>(tok + (size_t)gA * ROW_STRIDE);
        const float4* rsB = reinterpret_cast<const float4*>(tok + (size_t)sB * ROW_STRIDE);
        const float4* rgB = reinterpret_cast<const float4*>(tok + (size_t)gB * ROW_STRIDE);

        // 8 independent loads issued back-to-back
        const float4 sA0 = ldcs4(rsA + lane);
        const float4 gA0 = ldcs4(rgA + lane);
        const float4 sB0 = ldcs4(rsB + lane);
        const float4 gB0 = ldcs4(rgB + lane);
        const float4 sA1 = ldcs4(rsA + 32 + lane);
        const float4 gA1 = ldcs4(rgA + 32 + lane);
        const float4 sB1 = ldcs4(rsB + 32 + lane);
        const float4 gB1 = ldcs4(rgB + 32 + lane);

        float accA = 0.f, accB = 0.f;
        accA = fmaf(sA0.x * gA0.x, v0.x, accA);
        accA = fmaf(sA0.y * gA0.y, v0.y, accA);
        accA = fmaf(sA0.z * gA0.z, v0.z, accA);
        accA = fmaf(sA0.w * gA0.w, v0.w, accA);
        accA = fmaf(sA1.x * gA1.x, v1.x, accA);
        accA = fmaf(sA1.y * gA1.y, v1.y, accA);
        accA = fmaf(sA1.z * gA1.z, v1.z, accA);
        accA = fmaf(sA1.w * gA1.w, v1.w, accA);

        accB = fmaf(sB0.x * gB0.x, v0.x, accB);
        accB = fmaf(sB0.y * gB0.y, v0.y, accB);
        accB = fmaf(sB0.z * gB0.z, v0.z, accB);
        accB = fmaf(sB0.w * gB0.w, v0.w, accB);
        accB = fmaf(sB1.x * gB1.x, v1.x, accB);
        accB = fmaf(sB1.y * gB1.y, v1.y, accB);
        accB = fmaf(sB1.z * gB1.z, v1.z, accB);
        accB = fmaf(sB1.w * gB1.w, v1.w, accB);

        accA = warp_reduce_sum(accA);
        accB = warp_reduce_sum(accB);
        if (lane == 0) {
            out[e0] = accA + c;
            out[e1] = accB + c;
        }
    }
}

// ---------------------------------------------------------------------------
// lm phase: block per (batch, s-tile of 32). Loop over the batch's m's with
// the query row staged in smem; the 32KB candidate tile becomes L1-resident
// after the first m, eliminating ~500MB of repeated L2 reads.
// ---------------------------------------------------------------------------
__device__ __forceinline__ void lm_phase(
    const float* __restrict__ tok, const int* __restrict__ lm_idx,
    const int* __restrict__ tpm, float* __restrict__ out, int blk)
{
    const int b    = blk / N_TILES;
    const int tile = blk % N_TILES;
    const int s0   = tile * S_TILE;

    __shared__ float q[DD];

    const int t    = threadIdx.x;        // 256 threads
    const int lane = t & 31;
    const int warp = t >> 5;             // 0..7

    const int cnt = min(g_cnt[b], BATCH_CAP);
    const int* list = g_list + b * BATCH_CAP;

    const float* base = tok + ((size_t)b * SS + s0) * ROW_STRIDE;
    const int* mrow = tpm + (size_t)b * SS + s0;

    // Per-warp mask bits for its 4 s values (warp handles s0+warp, stride 8)
    for (int it = 0; it < cnt; it++) {
        const int m = list[it];
        __syncthreads();                 // protect q from previous iteration
        q[t] = tok[(size_t)lm_idx[m] * DD + t];
        __syncthreads();

        const float4* qv = reinterpret_cast<const float4*>(q);
        const float4 q0 = qv[lane];
        const float4 q1 = qv[32 + lane];

        float* orow = out + (size_t)E_EDGES + (size_t)m * SS + s0;

        #pragma unroll
        for (int si = warp; si < S_TILE; si += 8) {
            const float4* cr = reinterpret_cast<const float4*>(base + (size_t)si * ROW_STRIDE);
            const float4 c0 = cr[lane];
            const float4 c1 = cr[32 + lane];

            float acc = 0.f;
            acc = fmaf(q0.x, c0.x, acc);
            acc = fmaf(q0.y, c0.y, acc);
            acc = fmaf(q0.z, c0.z, acc);
            acc = fmaf(q0.w, c0.w, acc);
            acc = fmaf(q1.x, c1.x, acc);
            acc = fmaf(q1.y, c1.y, acc);
            acc = fmaf(q1.z, c1.z, acc);
            acc = fmaf(q1.w, c1.w, acc);

            acc = warp_reduce_sum(acc);
            if (lane == 0)
                orow[si] = (mrow[si] != 0) ? acc : NEG_INF_F;
        }
    }
}

// ---------------------------------------------------------------------------
__global__ __launch_bounds__(256)
void fused_kernel(const float* __restrict__ tok,
                  const int*   __restrict__ eidx,
                  const int*   __restrict__ lm_idx,
                  const int*   __restrict__ tpm,
                  float*       __restrict__ out)
{
    const int blk = blockIdx.x;
    if (blk < LEMMA_BLOCKS) {
        lemma_phase(tok, eidx, out, blk);
    } else {
        lm_phase(tok, lm_idx, tpm, out, blk - LEMMA_BLOCKS);
    }
}

// ---------------------------------------------------------------------------
// Inputs (metadata order):
//  0 token_reprs f32 [B,S,T,D]
//  1 w1 f32 [D, D/2]     2 b1 f32 [D/2]     3 w2 f32 [D/2,1]    4 b2 f32 [1]
//  5 edge_index i32 [2,E]  6 lm_indices i32 [M]  7 batch_pointers i32 [M]
//  8 tree_padding_mask (bool -> int32) [B,S]
// Output: float32, E lemmas followed by M*S lm_preds.
// ---------------------------------------------------------------------------
extern "C" void kernel_launch(void* const* d_in, const int* in_sizes, int n_in,
                              void* d_out, int out_size) {
    const float* tok  = (const float*)d_in[0];
    const float* w1   = (const float*)d_in[1];
    const float* b1   = (const float*)d_in[2];
    const float* w2   = (const float*)d_in[3];
    const float* b2   = (const float*)d_in[4];
    const int*   eidx = (const int*)d_in[5];
    const int*   lmi  = (const int*)d_in[6];
    const int*   bpt  = (const int*)d_in[7];
    const int*   tpm  = (const int*)d_in[8];
    float* out = (float*)d_out;

    prep_kernel<<<1, DD>>>(w1, b1, w2, b2);
    bucket_kernel<<<(M_CNT + 255) / 256, 256>>>(bpt);
    fused_kernel<<<TOTAL_BLOCKS, 256>>>(tok, eidx, lmi, tpm, out);
}

// round 7
// speedup vs baseline: 1.2738x; 1.2738x over previous
#include <cuda_runtime.h>

#define BB 64
#define SS 256
#define TT 8
#define DD 256
#define E_EDGES 500000
#define M_CNT 2048
#define ROW_STRIDE (TT * DD)   // 2048 floats between consecutive (b,s) type rows
#define NEG_INF_F (-10000000000.0f)

#define S_TILE 32
#define N_TILES (SS / S_TILE)             // 8
#define LM_BLOCKS (BB * N_TILES)          // 512
#define LEMMA_BLOCKS 2048
#define TOTAL_BLOCKS (LEMMA_BLOCKS + LM_BLOCKS)
#define BATCH_CAP 128                     // max m's per batch (mean 32)

// Folded linear head: v = w1 @ w2 (D floats), c = b1.w2 + b2
__device__ float g_v[DD];
__device__ float g_c;
// Per-batch m lists (rebuilt every launch)
__device__ int g_cnt[BB];
__device__ int g_list[BB * BATCH_CAP];

// ---------------------------------------------------------------------------
// Prep: blocks 0..7 fold the linear layers (warp computes 4 output d's,
// lane-parallel over k + shfl reduce). Block 8 buckets m indices by batch
// (self-contained: zeros counters, __syncthreads, atomics within one block).
// ---------------------------------------------------------------------------
__global__ void prep_kernel(const float* __restrict__ w1,   // [D, D/2]
                            const float* __restrict__ b1,   // [D/2]
                            const float* __restrict__ w2,   // [D/2, 1]
                            const float* __restrict__ b2,   // [1]
                            const int*   __restrict__ bptr) // [M]
{
    const int t    = threadIdx.x;        // 256 threads
    const int lane = t & 31;
    const int warp = t >> 5;             // 0..7

    if (blockIdx.x < 8) {
        const int d0 = blockIdx.x * 32 + warp * 4;
        #pragma unroll
        for (int j = 0; j < 4; j++) {
            const int d = d0 + j;
            const float* row = w1 + (size_t)d * (DD / 2);
            float acc = 0.f;
            #pragma unroll
            for (int k = lane; k < DD / 2; k += 32)
                acc = fmaf(row[k], w2[k], acc);
            #pragma unroll
            for (int off = 16; off > 0; off >>= 1)
                acc += __shfl_xor_sync(0xFFFFFFFFu, acc, off);
            if (lane == 0) g_v[d] = acc;
        }
        if (blockIdx.x == 0 && warp == 0) {
            float c = 0.f;
            #pragma unroll
            for (int k = lane; k < DD / 2; k += 32)
                c = fmaf(b1[k], w2[k], c);
            #pragma unroll
            for (int off = 16; off > 0; off >>= 1)
                c += __shfl_xor_sync(0xFFFFFFFFu, c, off);
            if (lane == 0) g_c = c + b2[0];
        }
    } else {
        if (t < BB) g_cnt[t] = 0;
        __syncthreads();
        for (int m = t; m < M_CNT; m += blockDim.x) {
            int b = bptr[m];
            int slot = atomicAdd(&g_cnt[b], 1);
            if (slot < BATCH_CAP) g_list[b * BATCH_CAP + slot] = m;
        }
    }
}

__device__ __forceinline__ float warp_reduce_sum(float v) {
    #pragma unroll
    for (int off = 16; off > 0; off >>= 1)
        v += __shfl_xor_sync(0xFFFFFFFFu, v, off);
    return v;
}

// ---------------------------------------------------------------------------
// Lemma phase: warp per 2 edges (8 independent LDG.128 in flight).
// Plain cached loads: the 16.7MB gather table must stay L2-resident.
// ---------------------------------------------------------------------------
__device__ __forceinline__ void lemma_phase(
    const float* __restrict__ tok, const int* __restrict__ eidx,
    float* __restrict__ out, int block)
{
    const int lane   = threadIdx.x & 31;
    const int warp   = (block * blockDim.x + threadIdx.x) >> 5;
    const int nwarps = (LEMMA_BLOCKS * blockDim.x) >> 5;

    const float4* vv = reinterpret_cast<const float4*>(g_v);
    const float4 v0 = vv[lane];
    const float4 v1 = vv[32 + lane];
    const float  c  = g_c;

    for (int p = warp; p < E_EDGES / 2; p += nwarps) {
        const int e0 = 2 * p;
        const int e1 = e0 + 1;
        const int sA = eidx[e0];
        const int gA = eidx[E_EDGES + e0];
        const int sB = eidx[e1];
        const int gB = eidx[E_EDGES + e1];

        const float4* rsA = reinterpret_cast<const float4*>(tok + (size_t)sA * ROW_STRIDE);
        const float4* rgA = reinterpret_cast<const float4*>(tok + (size_t)gA * ROW_STRIDE);
        const float4* rsB = reinterpret_cast<const float4*>(tok + (size_t)sB * ROW_STRIDE);
        const float4* rgB = reinterpret_cast<const float4*>(tok + (size_t)gB * ROW_STRIDE);

        const float4 sA0 = rsA[lane];
        const float4 gA0 = rgA[lane];
        const float4 sB0 = rsB[lane];
        const float4 gB0 = rgB[lane];
        const float4 sA1 = rsA[32 + lane];
        const float4 gA1 = rgA[32 + lane];
        const float4 sB1 = rsB[32 + lane];
        const float4 gB1 = rgB[32 + lane];

        float accA = 0.f, accB = 0.f;
        accA = fmaf(sA0.x * gA0.x, v0.x, accA);
        accA = fmaf(sA0.y * gA0.y, v0.y, accA);
        accA = fmaf(sA0.z * gA0.z, v0.z, accA);
        accA = fmaf(sA0.w * gA0.w, v0.w, accA);
        accA = fmaf(sA1.x * gA1.x, v1.x, accA);
        accA = fmaf(sA1.y * gA1.y, v1.y, accA);
        accA = fmaf(sA1.z * gA1.z, v1.z, accA);
        accA = fmaf(sA1.w * gA1.w, v1.w, accA);

        accB = fmaf(sB0.x * gB0.x, v0.x, accB);
        accB = fmaf(sB0.y * gB0.y, v0.y, accB);
        accB = fmaf(sB0.z * gB0.z, v0.z, accB);
        accB = fmaf(sB0.w * gB0.w, v0.w, accB);
        accB = fmaf(sB1.x * gB1.x, v1.x, accB);
        accB = fmaf(sB1.y * gB1.y, v1.y, accB);
        accB = fmaf(sB1.z * gB1.z, v1.z, accB);
        accB = fmaf(sB1.w * gB1.w, v1.w, accB);

        accA = warp_reduce_sum(accA);
        accB = warp_reduce_sum(accB);
        if (lane == 0) {
            out[e0] = accA + c;
            out[e1] = accB + c;
        }
    }
}

// ---------------------------------------------------------------------------
// lm phase: block per (batch, s-tile of 32); loop over the batch's m's.
// The 32KB candidate tile is L1-resident after the first m.
// ---------------------------------------------------------------------------
__device__ __forceinline__ void lm_phase(
    const float* __restrict__ tok, const int* __restrict__ lm_idx,
    const int* __restrict__ tpm, float* __restrict__ out, int blk)
{
    const int b    = blk / N_TILES;
    const int tile = blk % N_TILES;
    const int s0   = tile * S_TILE;

    __shared__ float q[DD];

    const int t    = threadIdx.x;
    const int lane = t & 31;
    const int warp = t >> 5;             // 0..7

    const int cnt = min(g_cnt[b], BATCH_CAP);
    const int* list = g_list + b * BATCH_CAP;

    const float* base = tok + ((size_t)b * SS + s0) * ROW_STRIDE;
    const int* mrow = tpm + (size_t)b * SS + s0;

    for (int it = 0; it < cnt; it++) {
        const int m = list[it];
        __syncthreads();
        q[t] = tok[(size_t)lm_idx[m] * DD + t];
        __syncthreads();

        const float4* qv = reinterpret_cast<const float4*>(q);
        const float4 q0 = qv[lane];
        const float4 q1 = qv[32 + lane];

        float* orow = out + (size_t)E_EDGES + (size_t)m * SS + s0;

        #pragma unroll
        for (int si = warp; si < S_TILE; si += 8) {
            const float4* cr = reinterpret_cast<const float4*>(base + (size_t)si * ROW_STRIDE);
            const float4 c0 = cr[lane];
            const float4 c1 = cr[32 + lane];

            float acc = 0.f;
            acc = fmaf(q0.x, c0.x, acc);
            acc = fmaf(q0.y, c0.y, acc);
            acc = fmaf(q0.z, c0.z, acc);
            acc = fmaf(q0.w, c0.w, acc);
            acc = fmaf(q1.x, c1.x, acc);
            acc = fmaf(q1.y, c1.y, acc);
            acc = fmaf(q1.z, c1.z, acc);
            acc = fmaf(q1.w, c1.w, acc);

            acc = warp_reduce_sum(acc);
            if (lane == 0)
                orow[si] = (mrow[si] != 0) ? acc : NEG_INF_F;
        }
    }
}

// ---------------------------------------------------------------------------
__global__ __launch_bounds__(256)
void fused_kernel(const float* __restrict__ tok,
                  const int*   __restrict__ eidx,
                  const int*   __restrict__ lm_idx,
                  const int*   __restrict__ tpm,
                  float*       __restrict__ out)
{
    const int blk = blockIdx.x;
    if (blk < LEMMA_BLOCKS) {
        lemma_phase(tok, eidx, out, blk);
    } else {
        lm_phase(tok, lm_idx, tpm, out, blk - LEMMA_BLOCKS);
    }
}

// ---------------------------------------------------------------------------
// Inputs (metadata order):
//  0 token_reprs f32 [B,S,T,D]
//  1 w1 f32 [D,D/2]  2 b1 f32 [D/2]  3 w2 f32 [D/2,1]  4 b2 f32 [1]
//  5 edge_index i32 [2,E]  6 lm_indices i32 [M]  7 batch_pointers i32 [M]
//  8 tree_padding_mask (bool -> int32) [B,S]
// Output: float32, E lemmas followed by M*S lm_preds.
// ---------------------------------------------------------------------------
extern "C" void kernel_launch(void* const* d_in, const int* in_sizes, int n_in,
                              void* d_out, int out_size) {
    const float* tok  = (const float*)d_in[0];
    const float* w1   = (const float*)d_in[1];
    const float* b1   = (const float*)d_in[2];
    const float* w2   = (const float*)d_in[3];
    const float* b2   = (const float*)d_in[4];
    const int*   eidx = (const int*)d_in[5];
    const int*   lmi  = (const int*)d_in[6];
    const int*   bpt  = (const int*)d_in[7];
    const int*   tpm  = (const int*)d_in[8];
    float* out = (float*)d_out;

    prep_kernel<<<9, 256>>>(w1, b1, w2, b2, bpt);
    fused_kernel<<<TOTAL_BLOCKS, 256>>>(tok, eidx, lmi, tpm, out);
}